// round 8
// baseline (speedup 1.0000x reference)
#include <cuda_runtime.h>

#define Bv 8
#define Cv 128
#define Hv 128
#define Wv 128
#define KK 9
#define NPLANES (Bv * Cv)
#define CONV_CTAS 444   /* 148 SMs x 3 */

typedef unsigned long long u64;

// Scratch (no allocations allowed in kernel_launch)
__device__ float g_pooled[Bv * Cv];
__device__ float g_h[Bv * Cv];
__device__ unsigned int g_ctr;

// ---- packed f32x2 helpers (Blackwell FFMA2 via PTX) ------------------------
__device__ __forceinline__ u64 pack2(float lo, float hi) {
    u64 r;
    asm("mov.b64 %0, {%1, %2};" : "=l"(r) : "f"(lo), "f"(hi));
    return r;
}
__device__ __forceinline__ u64 fma2(u64 a, u64 b, u64 c) {
    u64 d;
    asm("fma.rn.f32x2 %0, %1, %2, %3;" : "=l"(d) : "l"(a), "l"(b), "l"(c));
    return d;
}
__device__ __forceinline__ u64 mul2(u64 a, u64 b) {
    u64 d;
    asm("mul.rn.f32x2 %0, %1, %2;" : "=l"(d) : "l"(a), "l"(b));
    return d;
}
__device__ __forceinline__ void unpack2(u64 v, float& a, float& b) {
    asm("mov.b64 {%0, %1}, %2;" : "=f"(a), "=f"(b) : "l"(v));
}

// ---------------------------------------------------------------------------
// Kernel 1: global average pool per (b,c) plane. 1024 blocks x 256 threads.
// Also populates L2 with x for the conv pass.
// ---------------------------------------------------------------------------
__global__ void pool_kernel(const float* __restrict__ x) {
    const int plane = blockIdx.x;  // b*C + c
    const float4* xp = reinterpret_cast<const float4*>(x + (size_t)plane * Hv * Wv);

    float sum = 0.f;
#pragma unroll
    for (int i = 0; i < 16; i++) {
        float4 v = xp[threadIdx.x + i * 256];
        sum += (v.x + v.y) + (v.z + v.w);
    }

    __shared__ float sdata[8];
#pragma unroll
    for (int o = 16; o; o >>= 1) sum += __shfl_down_sync(0xffffffffu, sum, o);
    if ((threadIdx.x & 31) == 0) sdata[threadIdx.x >> 5] = sum;
    __syncthreads();
    if (threadIdx.x < 8) {
        sum = sdata[threadIdx.x];
#pragma unroll
        for (int o = 4; o; o >>= 1) sum += __shfl_down_sync(0xffu, sum, o);
        if (threadIdx.x == 0) g_pooled[plane] = sum * (1.f / (float)(Hv * Wv));
    }
}

// ---------------------------------------------------------------------------
// Kernel 2: h = relu(pooled @ w1^T + b1). 8 blocks x 128 threads, warp-dots.
// Also resets the conv work-steal counter.
// ---------------------------------------------------------------------------
__global__ void h_kernel(const float* __restrict__ w1, const float* __restrict__ b1) {
    const int b = blockIdx.x;
    const int tid = threadIdx.x;
    const int wid = tid >> 5;
    const int lane = tid & 31;

    if (b == 0 && tid == 0) g_ctr = 0;

    __shared__ float ps[Cv];
    ps[tid] = g_pooled[b * Cv + tid];
    __syncthreads();

    const float4 pv = *(const float4*)&ps[lane * 4];

#pragma unroll 4
    for (int i = 0; i < 32; i++) {
        const int o = wid * 32 + i;
        const float4 wv = *(const float4*)(w1 + (size_t)o * Cv + lane * 4);
        float acc = wv.x * pv.x;
        acc = fmaf(wv.y, pv.y, acc);
        acc = fmaf(wv.z, pv.z, acc);
        acc = fmaf(wv.w, pv.w, acc);
#pragma unroll
        for (int s = 16; s; s >>= 1) acc += __shfl_xor_sync(0xffffffffu, acc, s);
        if (lane == 0) g_h[b * Cv + o] = fmaxf(acc + b1[o], 0.f);
    }
}

// ---------------------------------------------------------------------------
// Kernel 3: persistent fused kern-gen + depthwise 3x3 conv.
// 444 CTAs x 256 threads (8 warps). Work-stealing over 1024 planes via a
// global atomic counter (output per plane is CTA-independent -> deterministic).
// Per plane: 8 warps compute the 9 kernel taps as warp-dots (warp 0 takes 2),
// then each warp convolves a 16-row strip with shfl halo, packed f32x2 FMAs,
// distance-1 row prefetch, streaming STG.128.
// ---------------------------------------------------------------------------
__global__ void __launch_bounds__(256, 3)
conv_kernel(const float* __restrict__ x,
            const float* __restrict__ w2, const float* __restrict__ b2,
            float* __restrict__ out) {
    const int wid = threadIdx.x >> 5;      // 0..7
    const int lane = threadIdx.x & 31;

    __shared__ float kw[KK];
    __shared__ unsigned int s_plane;

    for (;;) {
        if (threadIdx.x == 0) s_plane = atomicAdd(&g_ctr, 1u);
        __syncthreads();                    // also fences prior iter's kw reads
        const unsigned int plane = s_plane;
        if (plane >= NPLANES) break;

        const int b = plane >> 7;
        const int c = plane & 127;

        // --- per-plane kernel taps (9 warp-dots over C=128) ---
        {
            const float4 hv = ((const float4*)(g_h + b * Cv))[lane];
#pragma unroll
            for (int rep = 0; rep < 2; rep++) {
                const int p = wid + rep * 8;
                if (p < KK) {
                    const float4 wv = ((const float4*)(w2 + (size_t)(c * KK + p) * Cv))[lane];
                    float acc = wv.x * hv.x;
                    acc = fmaf(wv.y, hv.y, acc);
                    acc = fmaf(wv.z, hv.z, acc);
                    acc = fmaf(wv.w, hv.w, acc);
#pragma unroll
                    for (int s = 16; s; s >>= 1) acc += __shfl_xor_sync(0xffffffffu, acc, s);
                    if (lane == 0) kw[p] = acc + b2[c * KK + p];
                }
            }
        }
        __syncthreads();

        u64 w2p[9];
#pragma unroll
        for (int p = 0; p < 9; p++) w2p[p] = pack2(kw[p], kw[p]);

        // --- conv over this warp's 16-row strip, prefetch distance 1 ---
        const int row0 = wid * 16;
        const float* xp = x + (size_t)plane * Hv * Wv;
        float* op = out + (size_t)plane * Hv * Wv;

        // Load raw row as float4 (zero outside [0,H))
#define LOADF4(v, gr)                                                         \
        {                                                                     \
            if ((gr) < 0 || (gr) >= Hv) { v.x = v.y = v.z = v.w = 0.f; }      \
            else v = __ldg((const float4*)(xp + (gr) * Wv) + lane);           \
        }
        // Convert raw float4 row -> 5 packed pairs with shfl halo
#define CONVROW(d, v)                                                         \
        {                                                                     \
            float cm1 = __shfl_up_sync(0xffffffffu, v.w, 1);                  \
            float cp4 = __shfl_down_sync(0xffffffffu, v.x, 1);                \
            if (lane == 0) cm1 = 0.f;                                         \
            if (lane == 31) cp4 = 0.f;                                        \
            d[0] = pack2(cm1, v.x);                                           \
            d[1] = pack2(v.x, v.y);                                           \
            d[2] = pack2(v.y, v.z);                                           \
            d[3] = pack2(v.z, v.w);                                           \
            d[4] = pack2(v.w, cp4);                                           \
        }

        u64 r[3][5];
        {
            float4 v;
            LOADF4(v, row0 - 1); CONVROW(r[0], v);
            LOADF4(v, row0);     CONVROW(r[1], v);
        }
        float4 pf;
        LOADF4(pf, row0 + 1);   // row for first iteration's rb

#pragma unroll
        for (int i = 0; i < 16; i++) {
            // Issue prefetch for the NEXT iteration's bottom row first.
            float4 pf_next;
            LOADF4(pf_next, row0 + i + 2);

            u64* rt = r[i % 3];
            u64* rm = r[(i + 1) % 3];
            u64* rb = r[(i + 2) % 3];
            CONVROW(rb, pf);     // consume prefetched row (issued last iter)

            u64 accA = mul2(rt[0], w2p[0]);
            accA = fma2(rt[1], w2p[1], accA);
            accA = fma2(rt[2], w2p[2], accA);
            accA = fma2(rm[0], w2p[3], accA);
            accA = fma2(rm[1], w2p[4], accA);
            accA = fma2(rm[2], w2p[5], accA);
            accA = fma2(rb[0], w2p[6], accA);
            accA = fma2(rb[1], w2p[7], accA);
            accA = fma2(rb[2], w2p[8], accA);

            u64 accB = mul2(rt[2], w2p[0]);
            accB = fma2(rt[3], w2p[1], accB);
            accB = fma2(rt[4], w2p[2], accB);
            accB = fma2(rm[2], w2p[3], accB);
            accB = fma2(rm[3], w2p[4], accB);
            accB = fma2(rm[4], w2p[5], accB);
            accB = fma2(rb[2], w2p[6], accB);
            accB = fma2(rb[3], w2p[7], accB);
            accB = fma2(rb[4], w2p[8], accB);

            float4 o;
            unpack2(accA, o.x, o.y);
            unpack2(accB, o.z, o.w);
            __stcs((float4*)(op + (row0 + i) * Wv) + lane, o);

            pf = pf_next;
        }
#undef LOADF4
#undef CONVROW
    }
}

// ---------------------------------------------------------------------------
extern "C" void kernel_launch(void* const* d_in, const int* in_sizes, int n_in,
                              void* d_out, int out_size) {
    const float* x  = (const float*)d_in[0];
    const float* w1 = (const float*)d_in[1];
    const float* b1 = (const float*)d_in[2];
    const float* w2 = (const float*)d_in[3];
    const float* b2 = (const float*)d_in[4];
    float* out = (float*)d_out;

    pool_kernel<<<Bv * Cv, 256>>>(x);
    h_kernel<<<Bv, 128>>>(w1, b1);
    conv_kernel<<<CONV_CTAS, 256>>>(x, w2, b2, out);
}

// round 9
// speedup vs baseline: 1.0925x; 1.0925x over previous
#include <cuda_runtime.h>

#define Bv 8
#define Cv 128
#define Hv 128
#define Wv 128
#define KK 9
#define NPLANES (Bv * Cv)
#define CONV_CTAS 444   /* 148 SMs x 3 */

typedef unsigned long long u64;

// Scratch (no allocations allowed in kernel_launch)
__device__ float g_pooled[Bv * Cv];
__device__ float g_h[Bv * Cv];
__device__ unsigned int g_ctr;
__device__ unsigned int g_done[Bv];
__device__ volatile unsigned int g_hdone[Bv];

// ---- packed f32x2 helpers (Blackwell FFMA2 via PTX) ------------------------
__device__ __forceinline__ u64 pack2(float lo, float hi) {
    u64 r;
    asm("mov.b64 %0, {%1, %2};" : "=l"(r) : "f"(lo), "f"(hi));
    return r;
}
__device__ __forceinline__ u64 fma2(u64 a, u64 b, u64 c) {
    u64 d;
    asm("fma.rn.f32x2 %0, %1, %2, %3;" : "=l"(d) : "l"(a), "l"(b), "l"(c));
    return d;
}
__device__ __forceinline__ u64 mul2(u64 a, u64 b) {
    u64 d;
    asm("mul.rn.f32x2 %0, %1, %2;" : "=l"(d) : "l"(a), "l"(b));
    return d;
}
__device__ __forceinline__ void unpack2(u64 v, float& a, float& b) {
    asm("mov.b64 {%0, %1}, %2;" : "=f"(a), "=f"(b) : "l"(v));
}

// ---------------------------------------------------------------------------
// Kernel 0: reset pipeline state (graph replays need fresh state every call).
// ---------------------------------------------------------------------------
__global__ void init_kernel() {
    if (threadIdx.x < Bv) {
        g_done[threadIdx.x] = 0;
        g_hdone[threadIdx.x] = 0;
    }
    if (threadIdx.x == 0) g_ctr = 0;
}

// ---------------------------------------------------------------------------
// Kernel 1: persistent pipelined pool -> h -> kern+conv.
// Work items 0..1023   : pool plane i (batch-major).
// Work items 1024..2047: conv plane (i-1024), gated on h(batch) flag.
// The CTA that completes the last pool item of a batch computes h(b) in-CTA.
// ---------------------------------------------------------------------------
__global__ void __launch_bounds__(256, 3)
mega_kernel(const float* __restrict__ x,
            const float* __restrict__ w1, const float* __restrict__ b1,
            const float* __restrict__ w2, const float* __restrict__ b2,
            float* __restrict__ out) {
    const int tid = threadIdx.x;
    const int wid = tid >> 5;       // 0..7
    const int lane = tid & 31;

    __shared__ unsigned int s_item;
    __shared__ int s_do_h;
    __shared__ float sdata[8];
    __shared__ float kw[KK];

    for (;;) {
        if (tid == 0) s_item = atomicAdd(&g_ctr, 1u);
        __syncthreads();
        const unsigned int item = s_item;
        if (item >= 2u * NPLANES) break;

        if (item < NPLANES) {
            // ================= POOL (+ maybe h) =================
            const int plane = item;
            const int b = plane >> 7;
            const float4* xp = (const float4*)(x + (size_t)plane * Hv * Wv);

            float sum = 0.f;
#pragma unroll
            for (int i = 0; i < 16; i++) {
                float4 v = xp[tid + i * 256];
                sum += (v.x + v.y) + (v.z + v.w);
            }
#pragma unroll
            for (int o = 16; o; o >>= 1) sum += __shfl_down_sync(0xffffffffu, sum, o);
            if (lane == 0) sdata[wid] = sum;
            __syncthreads();
            if (tid == 0) {
                float t = sdata[0];
#pragma unroll
                for (int i = 1; i < 8; i++) t += sdata[i];
                g_pooled[plane] = t * (1.f / (float)(Hv * Wv));
                __threadfence();
                const unsigned int d = atomicAdd(&g_done[b], 1u);
                s_do_h = (d == Cv - 1);
            }
            __syncthreads();

            if (s_do_h) {
                // This CTA closed batch b's pool: compute h(b) = relu(pooled@w1^T+b1).
                __threadfence();  // order: observe all 128 pooled writes
                const float4 pv = __ldcg((const float4*)(g_pooled + b * Cv) + lane);
#pragma unroll 4
                for (int i = 0; i < 16; i++) {
                    const int o = wid * 16 + i;
                    const float4 wv = __ldg((const float4*)(w1 + (size_t)o * Cv) + lane);
                    float acc = wv.x * pv.x;
                    acc = fmaf(wv.y, pv.y, acc);
                    acc = fmaf(wv.z, pv.z, acc);
                    acc = fmaf(wv.w, pv.w, acc);
#pragma unroll
                    for (int s = 16; s; s >>= 1) acc += __shfl_xor_sync(0xffffffffu, acc, s);
                    if (lane == 0) g_h[b * Cv + o] = fmaxf(acc + b1[o], 0.f);
                }
                __syncthreads();
                if (tid == 0) {
                    __threadfence();
                    g_hdone[b] = 1u;   // release flag
                }
            }
        } else {
            // ================= KERN TAPS + CONV =================
            const int plane = item - NPLANES;
            const int b = plane >> 7;
            const int c = plane & 127;

            if (tid == 0) {
                while (g_hdone[b] == 0u) __nanosleep(64);
            }
            __syncthreads();
            __threadfence();  // acquire: g_h reads below must follow flag

            // 9 kernel taps: warp w handles taps w (and 8 for warp 0).
            {
                const float4 hv = __ldcg((const float4*)(g_h + b * Cv) + lane);
#pragma unroll
                for (int rep = 0; rep < 2; rep++) {
                    const int p = wid + rep * 8;
                    if (p < KK) {
                        const float4 wv = __ldg((const float4*)(w2 + (size_t)(c * KK + p) * Cv) + lane);
                        float acc = wv.x * hv.x;
                        acc = fmaf(wv.y, hv.y, acc);
                        acc = fmaf(wv.z, hv.z, acc);
                        acc = fmaf(wv.w, hv.w, acc);
#pragma unroll
                        for (int s = 16; s; s >>= 1) acc += __shfl_xor_sync(0xffffffffu, acc, s);
                        if (lane == 0) kw[p] = acc + b2[c * KK + p];
                    }
                }
            }
            __syncthreads();

            u64 w2p[9];
#pragma unroll
            for (int p = 0; p < 9; p++) w2p[p] = pack2(kw[p], kw[p]);

            const int row0 = wid * 16;
            const float* xp = x + (size_t)plane * Hv * Wv;
            float* op = out + (size_t)plane * Hv * Wv;

#define LOADROW(d, gr)                                                        \
            {                                                                 \
                if ((gr) < 0 || (gr) >= Hv) {                                 \
                    d[0] = 0; d[1] = 0; d[2] = 0; d[3] = 0; d[4] = 0;         \
                } else {                                                      \
                    float4 v = __ldg((const float4*)(xp + (gr) * Wv) + lane); \
                    float cm1 = __shfl_up_sync(0xffffffffu, v.w, 1);          \
                    float cp4 = __shfl_down_sync(0xffffffffu, v.x, 1);        \
                    if (lane == 0) cm1 = 0.f;                                 \
                    if (lane == 31) cp4 = 0.f;                                \
                    d[0] = pack2(cm1, v.x);                                   \
                    d[1] = pack2(v.x, v.y);                                   \
                    d[2] = pack2(v.y, v.z);                                   \
                    d[3] = pack2(v.z, v.w);                                   \
                    d[4] = pack2(v.w, cp4);                                   \
                }                                                             \
            }

            u64 r[3][5];
            LOADROW(r[0], row0 - 1);
            LOADROW(r[1], row0);

#pragma unroll
            for (int i = 0; i < 16; i++) {
                u64* rt = r[i % 3];
                u64* rm = r[(i + 1) % 3];
                u64* rb = r[(i + 2) % 3];
                LOADROW(rb, row0 + i + 1);

                u64 accA = mul2(rt[0], w2p[0]);
                accA = fma2(rt[1], w2p[1], accA);
                accA = fma2(rt[2], w2p[2], accA);
                accA = fma2(rm[0], w2p[3], accA);
                accA = fma2(rm[1], w2p[4], accA);
                accA = fma2(rm[2], w2p[5], accA);
                accA = fma2(rb[0], w2p[6], accA);
                accA = fma2(rb[1], w2p[7], accA);
                accA = fma2(rb[2], w2p[8], accA);

                u64 accB = mul2(rt[2], w2p[0]);
                accB = fma2(rt[3], w2p[1], accB);
                accB = fma2(rt[4], w2p[2], accB);
                accB = fma2(rm[2], w2p[3], accB);
                accB = fma2(rm[3], w2p[4], accB);
                accB = fma2(rm[4], w2p[5], accB);
                accB = fma2(rb[2], w2p[6], accB);
                accB = fma2(rb[3], w2p[7], accB);
                accB = fma2(rb[4], w2p[8], accB);

                float4 o;
                unpack2(accA, o.x, o.y);
                unpack2(accB, o.z, o.w);
                __stcs((float4*)(op + (row0 + i) * Wv) + lane, o);
            }
#undef LOADROW
        }
    }
}

// ---------------------------------------------------------------------------
extern "C" void kernel_launch(void* const* d_in, const int* in_sizes, int n_in,
                              void* d_out, int out_size) {
    const float* x  = (const float*)d_in[0];
    const float* w1 = (const float*)d_in[1];
    const float* b1 = (const float*)d_in[2];
    const float* w2 = (const float*)d_in[3];
    const float* b2 = (const float*)d_in[4];
    float* out = (float*)d_out;

    init_kernel<<<1, 32>>>();
    mega_kernel<<<CONV_CTAS, 256>>>(x, w1, b1, w2, b2, out);
}

// round 10
// speedup vs baseline: 1.1533x; 1.0557x over previous
#include <cuda_runtime.h>

#define Bv 8
#define Cv 128
#define Hv 128
#define Wv 128
#define KK 9
#define NPLANES (Bv * Cv)
#define CONV_CTAS 592   /* 148 SMs x 4 */

// Scratch (no allocations allowed in kernel_launch)
__device__ float g_pooled[Bv * Cv];
__device__ float g_h[Bv * Cv];
__device__ unsigned int g_ctr;
__device__ unsigned int g_done[Bv];
__device__ volatile unsigned int g_hdone[Bv];

// ---------------------------------------------------------------------------
// Kernel 0: reset pipeline state (graph replays need fresh state every call).
// ---------------------------------------------------------------------------
__global__ void init_kernel() {
    if (threadIdx.x < Bv) {
        g_done[threadIdx.x] = 0;
        g_hdone[threadIdx.x] = 0;
    }
    if (threadIdx.x == 0) g_ctr = 0;
}

// ---------------------------------------------------------------------------
// Kernel 1: persistent pipelined pool -> h -> kern+conv.
// Work items 0..1023   : pool plane i (batch-major).
// Work items 1024..2047: conv plane (i-1024), gated on h(batch) flag.
// Conv: scalar FMA, 6-float register rows, 4-row batched loads (MLP=4).
// ---------------------------------------------------------------------------
__global__ void __launch_bounds__(256, 4)
mega_kernel(const float* __restrict__ x,
            const float* __restrict__ w1, const float* __restrict__ b1,
            const float* __restrict__ w2, const float* __restrict__ b2,
            float* __restrict__ out) {
    const int tid = threadIdx.x;
    const int wid = tid >> 5;       // 0..7
    const int lane = tid & 31;

    __shared__ unsigned int s_item;
    __shared__ int s_do_h;
    __shared__ float sdata[8];
    __shared__ float kw[KK];

    for (;;) {
        if (tid == 0) s_item = atomicAdd(&g_ctr, 1u);
        __syncthreads();
        const unsigned int item = s_item;
        if (item >= 2u * NPLANES) break;

        if (item < NPLANES) {
            // ================= POOL (+ maybe h) =================
            const int plane = item;
            const int b = plane >> 7;
            const float4* xp = (const float4*)(x + (size_t)plane * Hv * Wv);

            float sum = 0.f;
#pragma unroll
            for (int i = 0; i < 16; i++) {
                float4 v = xp[tid + i * 256];
                sum += (v.x + v.y) + (v.z + v.w);
            }
#pragma unroll
            for (int o = 16; o; o >>= 1) sum += __shfl_down_sync(0xffffffffu, sum, o);
            if (lane == 0) sdata[wid] = sum;
            __syncthreads();
            if (tid == 0) {
                float t = sdata[0];
#pragma unroll
                for (int i = 1; i < 8; i++) t += sdata[i];
                g_pooled[plane] = t * (1.f / (float)(Hv * Wv));
                __threadfence();
                const unsigned int d = atomicAdd(&g_done[b], 1u);
                s_do_h = (d == Cv - 1);
            }
            __syncthreads();

            if (s_do_h) {
                __threadfence();  // observe all 128 pooled writes
                const float4 pv = __ldcg((const float4*)(g_pooled + b * Cv) + lane);
#pragma unroll 4
                for (int i = 0; i < 16; i++) {
                    const int o = wid * 16 + i;
                    const float4 wv = __ldg((const float4*)(w1 + (size_t)o * Cv) + lane);
                    float acc = wv.x * pv.x;
                    acc = fmaf(wv.y, pv.y, acc);
                    acc = fmaf(wv.z, pv.z, acc);
                    acc = fmaf(wv.w, pv.w, acc);
#pragma unroll
                    for (int s = 16; s; s >>= 1) acc += __shfl_xor_sync(0xffffffffu, acc, s);
                    if (lane == 0) g_h[b * Cv + o] = fmaxf(acc + b1[o], 0.f);
                }
                __syncthreads();
                if (tid == 0) {
                    __threadfence();
                    g_hdone[b] = 1u;   // release flag
                }
            }
        } else {
            // ================= KERN TAPS + CONV =================
            const int plane = item - NPLANES;
            const int b = plane >> 7;
            const int c = plane & 127;

            if (tid == 0) {
                while (g_hdone[b] == 0u) __nanosleep(64);
            }
            __syncthreads();
            __threadfence();  // acquire before g_h reads

            {
                const float4 hv = __ldcg((const float4*)(g_h + b * Cv) + lane);
#pragma unroll
                for (int rep = 0; rep < 2; rep++) {
                    const int p = wid + rep * 8;
                    if (p < KK) {
                        const float4 wv = __ldg((const float4*)(w2 + (size_t)(c * KK + p) * Cv) + lane);
                        float acc = wv.x * hv.x;
                        acc = fmaf(wv.y, hv.y, acc);
                        acc = fmaf(wv.z, hv.z, acc);
                        acc = fmaf(wv.w, hv.w, acc);
#pragma unroll
                        for (int s = 16; s; s >>= 1) acc += __shfl_xor_sync(0xffffffffu, acc, s);
                        if (lane == 0) kw[p] = acc + b2[c * KK + p];
                    }
                }
            }
            __syncthreads();

            float w[9];
#pragma unroll
            for (int p = 0; p < 9; p++) w[p] = kw[p];

            const int row0 = wid * 16;
            const float* xp = x + (size_t)plane * Hv * Wv;
            float* op = out + (size_t)plane * Hv * Wv;

            // Raw row load (zero outside bounds)
#define LOADF4(v, gr)                                                         \
            {                                                                 \
                if ((gr) < 0 || (gr) >= Hv) { v.x = v.y = v.z = v.w = 0.f; }  \
                else v = __ldg((const float4*)(xp + (gr) * Wv) + lane);       \
            }
            // float4 + shfl halo -> 6-float row [cm1, x, y, z, w, cp4]
#define CONVROW(a, v)                                                         \
            {                                                                 \
                float cm1 = __shfl_up_sync(0xffffffffu, v.w, 1);              \
                float cp4 = __shfl_down_sync(0xffffffffu, v.x, 1);            \
                if (lane == 0) cm1 = 0.f;                                     \
                if (lane == 31) cp4 = 0.f;                                    \
                a[0] = cm1; a[1] = v.x; a[2] = v.y;                           \
                a[3] = v.z; a[4] = v.w; a[5] = cp4;                           \
            }
            // One output row from 3 input rows (scalar FMA, 36 flops)
#define OUTROW(gr, X, Y, Z)                                                   \
            {                                                                 \
                float4 o;                                                     \
                float* po = &o.x;                                             \
                _Pragma("unroll")                                             \
                for (int k = 0; k < 4; k++) {                                 \
                    float acc = X[k] * w[0];                                  \
                    acc = fmaf(X[k + 1], w[1], acc);                          \
                    acc = fmaf(X[k + 2], w[2], acc);                          \
                    acc = fmaf(Y[k],     w[3], acc);                          \
                    acc = fmaf(Y[k + 1], w[4], acc);                          \
                    acc = fmaf(Y[k + 2], w[5], acc);                          \
                    acc = fmaf(Z[k],     w[6], acc);                          \
                    acc = fmaf(Z[k + 1], w[7], acc);                          \
                    acc = fmaf(Z[k + 2], w[8], acc);                          \
                    po[k] = acc;                                              \
                }                                                             \
                __stcs((float4*)(op + (gr) * Wv) + lane, o);                  \
            }

            float A[6], B[6], C[6], D[6], E[6], F[6];
            {
                float4 v;
                LOADF4(v, row0 - 1); CONVROW(A, v);
                LOADF4(v, row0);     CONVROW(B, v);
            }

#pragma unroll
            for (int ch = 0; ch < 4; ch++) {
                const int obase = row0 + ch * 4;
                // batch-issue 4 independent row loads (MLP = 4)
                float4 p0, p1, p2, p3;
                LOADF4(p0, obase + 1);
                LOADF4(p1, obase + 2);
                LOADF4(p2, obase + 3);
                LOADF4(p3, obase + 4);
                CONVROW(C, p0);
                CONVROW(D, p1);
                CONVROW(E, p2);
                CONVROW(F, p3);

                OUTROW(obase + 0, A, B, C);
                OUTROW(obase + 1, B, C, D);
                OUTROW(obase + 2, C, D, E);
                OUTROW(obase + 3, D, E, F);

                // carry last two input rows into next chunk
#pragma unroll
                for (int q = 0; q < 6; q++) { A[q] = E[q]; B[q] = F[q]; }
            }
#undef LOADF4
#undef CONVROW
#undef OUTROW
        }
    }
}

// ---------------------------------------------------------------------------
extern "C" void kernel_launch(void* const* d_in, const int* in_sizes, int n_in,
                              void* d_out, int out_size) {
    const float* x  = (const float*)d_in[0];
    const float* w1 = (const float*)d_in[1];
    const float* b1 = (const float*)d_in[2];
    const float* w2 = (const float*)d_in[3];
    const float* b2 = (const float*)d_in[4];
    float* out = (float*)d_out;

    init_kernel<<<1, 32>>>();
    mega_kernel<<<CONV_CTAS, 256>>>(x, w1, b1, w2, b2, out);
}